// round 4
// baseline (speedup 1.0000x reference)
#include <cuda_runtime.h>
#include <cuda_bf16.h>
#include <cstdint>

#define N   16384
#define D   256
#define NT  128
#define TM  128
#define TEMP_SCALE 20.60964047443681f   // 1/(0.07*ln2)

#define PITCHW 132                       // smem row pitch in 32-bit words (264 bf16)

// ---- device scratch (no allocation allowed) ----
__device__ __nv_bfloat16 g_embh[N * D];   // normalized embeddings, bf16, 8 MB
__device__ float         g_part[NT][N];   // partial exp-sums [col_tile][row], 8 MB
__device__ double        g_bsum[N / 256]; // per-block log partials

// ---------------------------------------------------------------------------
// Kernel 1: L2-normalize rows -> bf16. One warp per row, 8 rows per block.
// ---------------------------------------------------------------------------
__global__ void k_normalize(const float* __restrict__ in) {
    const int warp = threadIdx.x >> 5;
    const int lane = threadIdx.x & 31;
    const int row  = blockIdx.x * 8 + warp;

    const float4* rp = reinterpret_cast<const float4*>(in) + (size_t)row * (D / 4);
    float4 v0 = rp[lane];
    float4 v1 = rp[lane + 32];

    float ss = v0.x * v0.x + v0.y * v0.y + v0.z * v0.z + v0.w * v0.w
             + v1.x * v1.x + v1.y * v1.y + v1.z * v1.z + v1.w * v1.w;
    #pragma unroll
    for (int off = 16; off; off >>= 1)
        ss += __shfl_xor_sync(0xffffffffu, ss, off);

    const float inv = 1.0f / fmaxf(sqrtf(ss), 1e-12f);

    __nv_bfloat162 p0 = __floats2bfloat162_rn(v0.x * inv, v0.y * inv);
    __nv_bfloat162 p1 = __floats2bfloat162_rn(v0.z * inv, v0.w * inv);
    __nv_bfloat162 p2 = __floats2bfloat162_rn(v1.x * inv, v1.y * inv);
    __nv_bfloat162 p3 = __floats2bfloat162_rn(v1.z * inv, v1.w * inv);

    uint2 u0, u1;
    u0.x = *reinterpret_cast<uint32_t*>(&p0); u0.y = *reinterpret_cast<uint32_t*>(&p1);
    u1.x = *reinterpret_cast<uint32_t*>(&p2); u1.y = *reinterpret_cast<uint32_t*>(&p3);

    uint2* op = reinterpret_cast<uint2*>(g_embh + (size_t)row * D);
    op[lane]      = u0;
    op[lane + 32] = u1;
}

// ---------------------------------------------------------------------------
// mma.sync m16n8k16 bf16 (row.col) -> fp32 accum. Baseline PTX, HMMA SASS.
// ---------------------------------------------------------------------------
static __device__ __forceinline__ void mma16816(
    float& d0, float& d1, float& d2, float& d3,
    uint32_t a0, uint32_t a1, uint32_t a2, uint32_t a3,
    uint32_t b0, uint32_t b1)
{
    asm volatile(
        "mma.sync.aligned.m16n8k16.row.col.f32.bf16.bf16.f32 "
        "{%0,%1,%2,%3}, {%4,%5,%6,%7}, {%8,%9}, {%0,%1,%2,%3};"
        : "+f"(d0), "+f"(d1), "+f"(d2), "+f"(d3)
        : "r"(a0), "r"(a1), "r"(a2), "r"(a3), "r"(b0), "r"(b1));
}

// ---------------------------------------------------------------------------
// Kernel 2: 128x256 macro-tile (two 128x128 output tiles sharing the A tile).
// Grid (NT/2, NT): block (bjp, bi) covers bj0=2*bjp, bj1=bj0+1; live iff
// bj1 >= bi. 256 threads = 8 warps in 2x4 grid of 64x64 warp tiles.
// ---------------------------------------------------------------------------
__global__ __launch_bounds__(256, 1) void k_tiles() {
    const int bjp = blockIdx.x;
    const int bi  = blockIdx.y;
    const int bj0 = bjp * 2;
    const int bj1 = bj0 + 1;
    if (bj1 < bi) return;
    const bool do0 = (bj0 >= bi);

    extern __shared__ __align__(16) uint32_t smem_u[];
    uint32_t* As = smem_u;                    // [128][PITCHW] words (2 bf16/word)
    uint32_t* Bs = smem_u + 128 * PITCHW;     // [256][PITCHW]  rows 0..127=bj0, 128..255=bj1

    const int tid  = threadIdx.x;
    const int lane = tid & 31;
    const int wid  = tid >> 5;
    const int wr   = wid >> 2;      // warp row 0..1  (64 rows each)
    const int wc   = wid & 3;       // warp col 0..3  (64 cols each)
    const int g    = lane >> 2;     // group id 0..7
    const int t    = lane & 3;      // thread-in-group 0..3

    // ---- load A (tile bi) and B0|B1 (tiles bj0,bj1) into smem, row-major,
    //      pitch 132 words: fragment LDS bank pattern (4*row + t) -> conflict-free
    {
        const uint4* ga  = reinterpret_cast<const uint4*>(g_embh) + (size_t)bi  * TM * (D / 8);
        const uint4* gb0 = reinterpret_cast<const uint4*>(g_embh) + (size_t)bj0 * TM * (D / 8);
        const uint4* gb1 = reinterpret_cast<const uint4*>(g_embh) + (size_t)bj1 * TM * (D / 8);
        // A: 128 rows x 32 uint4-chunks = 4096; 16 per thread
        #pragma unroll
        for (int i = 0; i < 16; ++i) {
            const int idx = i * 256 + tid;
            const int row = idx >> 5;
            const int ch  = idx & 31;
            *reinterpret_cast<uint4*>(&As[row * PITCHW + ch * 4]) = ga[row * (D / 8) + ch];
        }
        // B: 2 x 128 rows
        #pragma unroll
        for (int i = 0; i < 16; ++i) {
            const int idx = i * 256 + tid;
            const int row = idx >> 5;
            const int ch  = idx & 31;
            *reinterpret_cast<uint4*>(&Bs[row * PITCHW + ch * 4]) = gb0[row * (D / 8) + ch];
            *reinterpret_cast<uint4*>(&Bs[(row + 128) * PITCHW + ch * 4]) = gb1[row * (D / 8) + ch];
        }
    }
    __syncthreads();

    // ---- main loop: 16 k-atoms of k16; warp tile 64x64 = 4 m-atoms x 8 n-atoms
    float acc[4][8][4];
    #pragma unroll
    for (int mi = 0; mi < 4; ++mi)
        #pragma unroll
        for (int ni = 0; ni < 8; ++ni)
            #pragma unroll
            for (int q = 0; q < 4; ++q)
                acc[mi][ni][q] = 0.0f;

    const int arow0 = wr * 64 + g;          // + mi*16 (+8 for upper frag regs)
    const int bcol0 = wc * 64 + g;          // + ni*8

    #pragma unroll 1
    for (int ka = 0; ka < 16; ++ka) {
        const int kw = ka * 8;              // k-atom start, in words

        uint32_t af[4][4];
        #pragma unroll
        for (int mi = 0; mi < 4; ++mi) {
            const uint32_t* ar = &As[(arow0 + mi * 16) * PITCHW + kw + t];
            af[mi][0] = ar[0];
            af[mi][1] = ar[8 * PITCHW];
            af[mi][2] = ar[4];
            af[mi][3] = ar[8 * PITCHW + 4];
        }
        uint32_t bf[8][2];
        #pragma unroll
        for (int ni = 0; ni < 8; ++ni) {
            const uint32_t* br = &Bs[(bcol0 + ni * 8) * PITCHW + kw + t];
            bf[ni][0] = br[0];
            bf[ni][1] = br[4];
        }
        #pragma unroll
        for (int mi = 0; mi < 4; ++mi)
            #pragma unroll
            for (int ni = 0; ni < 8; ++ni)
                mma16816(acc[mi][ni][0], acc[mi][ni][1], acc[mi][ni][2], acc[mi][ni][3],
                         af[mi][0], af[mi][1], af[mi][2], af[mi][3],
                         bf[ni][0], bf[ni][1]);
    }
    __syncthreads();   // operand smem free for epilogue buffers

    // ---- epilogue: exp + exact diagonal + row/col sums ----
    // element (mi,ni,q): row = wr*64 + mi*16 + g + (q>>1)*8
    //                    col = wc*64 + ni*8 + t*2 + (q&1)
    float* rbuf = reinterpret_cast<float*>(smem_u);            // [4 wc][128 rows]
    float* cbuf = reinterpret_cast<float*>(smem_u + 4 * 128);  // [2 wr][256 cols]

    const int tile_of_wc = wc >> 1;                 // 0 -> bj0, 1 -> bj1
    const int bj_of_wc   = tile_of_wc ? bj1 : bj0;
    const bool diag      = (bj_of_wc == bi);

    #pragma unroll
    for (int mi = 0; mi < 4; ++mi)
        #pragma unroll
        for (int ni = 0; ni < 8; ++ni)
            #pragma unroll
            for (int q = 0; q < 4; ++q) {
                float e = exp2f((acc[mi][ni][q] - 1.0f) * TEMP_SCALE);
                if (diag) {
                    const int r = wr * 64 + mi * 16 + g + (q >> 1) * 8;
                    const int c = (wc & 1) * 64 + ni * 8 + t * 2 + (q & 1);
                    if (r == c) e = 1.0f;           // s_ii == 1 exactly
                }
                acc[mi][ni][q] = e;
            }

    // row sums: per lane 8 rows (mi x rowhalf), reduce over t-lanes
    #pragma unroll
    for (int mi = 0; mi < 4; ++mi)
        #pragma unroll
        for (int h = 0; h < 2; ++h) {
            float rs = 0.0f;
            #pragma unroll
            for (int ni = 0; ni < 8; ++ni)
                rs += acc[mi][ni][2 * h] + acc[mi][ni][2 * h + 1];
            rs += __shfl_xor_sync(0xffffffffu, rs, 1);
            rs += __shfl_xor_sync(0xffffffffu, rs, 2);
            if (t == 0)
                rbuf[wc * 128 + wr * 64 + mi * 16 + g + h * 8] = rs;
        }

    // col sums: per lane 16 cols (ni x b), reduce over g-lanes
    #pragma unroll
    for (int ni = 0; ni < 8; ++ni)
        #pragma unroll
        for (int b = 0; b < 2; ++b) {
            float cs = 0.0f;
            #pragma unroll
            for (int mi = 0; mi < 4; ++mi)
                cs += acc[mi][ni][b] + acc[mi][ni][2 + b];
            cs += __shfl_xor_sync(0xffffffffu, cs, 4);
            cs += __shfl_xor_sync(0xffffffffu, cs, 8);
            cs += __shfl_xor_sync(0xffffffffu, cs, 16);
            if (g == 0)
                cbuf[wr * 256 + wc * 64 + ni * 8 + t * 2 + b] = cs;
        }
    __syncthreads();

    // final writes: unique writer per g_part cell
    if (tid < 128) {                        // row sums of both tiles
        const int row = tid;
        if (do0)
            g_part[bj0][bi * TM + row] = rbuf[0 * 128 + row] + rbuf[1 * 128 + row];
        g_part[bj1][bi * TM + row] = rbuf[2 * 128 + row] + rbuf[3 * 128 + row];
    }
    {                                       // col sums via symmetry (off-diag only)
        const int col  = tid;               // 0..255
        const int tile = col >> 7;
        const int bj   = tile ? bj1 : bj0;
        if (bj != bi && (tile == 1 || do0))
            g_part[bi][bj * TM + (col & 127)] =
                cbuf[0 * 256 + col] + cbuf[1 * 256 + col];
    }
}

// ---------------------------------------------------------------------------
// Kernel 3: per-row S_i = sum of 128 tile partials (double), log, block-sum.
// ---------------------------------------------------------------------------
__global__ void k_rowreduce() {
    const int r = blockIdx.x * 256 + threadIdx.x;
    double s = 0.0;
    #pragma unroll 8
    for (int j = 0; j < NT; ++j)
        s += (double)g_part[j][r];
    double lr = log(s);

    __shared__ double red[256];
    red[threadIdx.x] = lr;
    __syncthreads();
    #pragma unroll
    for (int off = 128; off; off >>= 1) {
        if (threadIdx.x < off) red[threadIdx.x] += red[threadIdx.x + off];
        __syncthreads();
    }
    if (threadIdx.x == 0) g_bsum[blockIdx.x] = red[0];
}

// ---------------------------------------------------------------------------
// Kernel 4: final mean over 64 block partials.
// ---------------------------------------------------------------------------
__global__ void k_final(float* __restrict__ out) {
    double v = g_bsum[threadIdx.x];
    #pragma unroll
    for (int off = 16; off; off >>= 1)
        v += __shfl_xor_sync(0xffffffffu, v, off);
    __shared__ double w[2];
    if ((threadIdx.x & 31) == 0) w[threadIdx.x >> 5] = v;
    __syncthreads();
    if (threadIdx.x == 0)
        out[0] = (float)((w[0] + w[1]) * (1.0 / (double)N));
}

// ---------------------------------------------------------------------------
#define SMEM_BYTES ((128 + 256) * PITCHW * 4)

extern "C" void kernel_launch(void* const* d_in, const int* in_sizes, int n_in,
                              void* d_out, int out_size) {
    const float* emb = (const float*)d_in[0];
    (void)in_sizes; (void)n_in; (void)out_size;

    cudaFuncSetAttribute(k_tiles, cudaFuncAttributeMaxDynamicSharedMemorySize, SMEM_BYTES);

    k_normalize<<<N / 8, 256>>>(emb);
    dim3 grid(NT / 2, NT);
    k_tiles<<<grid, 256, SMEM_BYTES>>>();
    k_rowreduce<<<N / 256, 256>>>();
    k_final<<<1, 64>>>((float*)d_out);
}

// round 16
// speedup vs baseline: 1.0138x; 1.0138x over previous
#include <cuda_runtime.h>
#include <cuda_bf16.h>
#include <cstdint>

#define N   16384
#define D   256
#define NT  128
#define TM  128
#define TEMP_SCALE 20.60964047443681f   // 1/(0.07*ln2)

#define PITCHW 132                       // smem row pitch in 32-bit words (264 bf16)

// ---- device scratch (no allocation allowed) ----
__device__ __nv_bfloat16 g_embh[N * D];   // normalized embeddings, bf16, 8 MB
__device__ float         g_part[NT][N];   // partial exp-sums [col_tile][row], 8 MB
__device__ double        g_bsum[N / 256]; // per-block log partials

// ---------------------------------------------------------------------------
// Kernel 1: L2-normalize rows -> bf16. One warp per row, 8 rows per block.
// ---------------------------------------------------------------------------
__global__ void k_normalize(const float* __restrict__ in) {
    const int warp = threadIdx.x >> 5;
    const int lane = threadIdx.x & 31;
    const int row  = blockIdx.x * 8 + warp;

    const float4* rp = reinterpret_cast<const float4*>(in) + (size_t)row * (D / 4);
    float4 v0 = rp[lane];
    float4 v1 = rp[lane + 32];

    float ss = v0.x * v0.x + v0.y * v0.y + v0.z * v0.z + v0.w * v0.w
             + v1.x * v1.x + v1.y * v1.y + v1.z * v1.z + v1.w * v1.w;
    #pragma unroll
    for (int off = 16; off; off >>= 1)
        ss += __shfl_xor_sync(0xffffffffu, ss, off);

    const float inv = 1.0f / fmaxf(sqrtf(ss), 1e-12f);

    __nv_bfloat162 p0 = __floats2bfloat162_rn(v0.x * inv, v0.y * inv);
    __nv_bfloat162 p1 = __floats2bfloat162_rn(v0.z * inv, v0.w * inv);
    __nv_bfloat162 p2 = __floats2bfloat162_rn(v1.x * inv, v1.y * inv);
    __nv_bfloat162 p3 = __floats2bfloat162_rn(v1.z * inv, v1.w * inv);

    uint2 u0, u1;
    u0.x = *reinterpret_cast<uint32_t*>(&p0); u0.y = *reinterpret_cast<uint32_t*>(&p1);
    u1.x = *reinterpret_cast<uint32_t*>(&p2); u1.y = *reinterpret_cast<uint32_t*>(&p3);

    uint2* op = reinterpret_cast<uint2*>(g_embh + (size_t)row * D);
    op[lane]      = u0;
    op[lane + 32] = u1;
}

// ---------------------------------------------------------------------------
// mma.sync m16n8k16 bf16 (row.col) -> fp32 accum (HMMA SASS).
// ---------------------------------------------------------------------------
static __device__ __forceinline__ void mma16816(
    float& d0, float& d1, float& d2, float& d3,
    uint32_t a0, uint32_t a1, uint32_t a2, uint32_t a3,
    uint32_t b0, uint32_t b1)
{
    asm volatile(
        "mma.sync.aligned.m16n8k16.row.col.f32.bf16.bf16.f32 "
        "{%0,%1,%2,%3}, {%4,%5,%6,%7}, {%8,%9}, {%0,%1,%2,%3};"
        : "+f"(d0), "+f"(d1), "+f"(d2), "+f"(d3)
        : "r"(a0), "r"(a1), "r"(a2), "r"(a3), "r"(b0), "r"(b1));
}

static __device__ __forceinline__ void ldsm_x4(
    uint32_t& r0, uint32_t& r1, uint32_t& r2, uint32_t& r3, uint32_t saddr)
{
    asm volatile("ldmatrix.sync.aligned.m8n8.x4.shared.b16 {%0,%1,%2,%3}, [%4];"
                 : "=r"(r0), "=r"(r1), "=r"(r2), "=r"(r3) : "r"(saddr));
}

// ---------------------------------------------------------------------------
// Kernel 2: 128x256 macro-tile (two 128x128 output tiles sharing the A tile).
// Grid (NT/2, NT): block (bjp, bi) covers bj0=2*bjp, bj1=bj0+1; live iff
// bj1 >= bi. 256 threads = 8 warps in 2x4 grid of 64x64 warp tiles.
// Main loop: ldmatrix.x4 fragment loads, 2-deep k-atom register pipeline.
// ---------------------------------------------------------------------------
__global__ __launch_bounds__(256, 1) void k_tiles() {
    const int bjp = blockIdx.x;
    const int bi  = blockIdx.y;
    const int bj0 = bjp * 2;
    const int bj1 = bj0 + 1;
    if (bj1 < bi) return;
    const bool do0 = (bj0 >= bi);

    extern __shared__ __align__(16) uint32_t smem_u[];
    uint32_t* As = smem_u;                    // [128][PITCHW] words (2 bf16/word)
    uint32_t* Bs = smem_u + 128 * PITCHW;     // [256][PITCHW]  rows 0..127=bj0, 128..255=bj1

    const int tid  = threadIdx.x;
    const int lane = tid & 31;
    const int wid  = tid >> 5;
    const int wr   = wid >> 2;      // warp row 0..1  (64 rows each)
    const int wc   = wid & 3;       // warp col 0..3  (64 cols each)
    const int g    = lane >> 2;     // group id 0..7
    const int t    = lane & 3;      // thread-in-group 0..3

    // ---- stage A (tile bi) and B0|B1 (tiles bj0,bj1) into smem ----
    {
        const uint4* ga  = reinterpret_cast<const uint4*>(g_embh) + (size_t)bi  * TM * (D / 8);
        const uint4* gb0 = reinterpret_cast<const uint4*>(g_embh) + (size_t)bj0 * TM * (D / 8);
        const uint4* gb1 = reinterpret_cast<const uint4*>(g_embh) + (size_t)bj1 * TM * (D / 8);
        #pragma unroll
        for (int i = 0; i < 16; ++i) {
            const int idx = i * 256 + tid;
            const int row = idx >> 5;
            const int ch  = idx & 31;
            *reinterpret_cast<uint4*>(&As[row * PITCHW + ch * 4]) = ga[row * (D / 8) + ch];
        }
        #pragma unroll
        for (int i = 0; i < 16; ++i) {
            const int idx = i * 256 + tid;
            const int row = idx >> 5;
            const int ch  = idx & 31;
            *reinterpret_cast<uint4*>(&Bs[row * PITCHW + ch * 4]) = gb0[row * (D / 8) + ch];
            *reinterpret_cast<uint4*>(&Bs[(row + 128) * PITCHW + ch * 4]) = gb1[row * (D / 8) + ch];
        }
    }
    __syncthreads();

    // ---- per-lane ldmatrix base addresses (bytes, shared space) ----
    // A, m-atom mi: lane groups (lane>>3): 0=(r+0,klo) 1=(r+8,klo) 2=(r+0,khi) 3=(r+8,khi)
    // B, n-pair np: lane groups:           0=(n+0,klo) 1=(n+0,khi) 2=(n+8,klo) 3=(n+8,khi)
    uint32_t a_addr[4], b_addr[4];
    {
        const uint32_t sa = (uint32_t)__cvta_generic_to_shared(As);
        const uint32_t sb = (uint32_t)__cvta_generic_to_shared(Bs);
        const int grp = lane >> 3;
        const int l7  = lane & 7;
        const int arow_off = (grp & 1) * 8;
        const int akh      = (grp >> 1) & 1;
        #pragma unroll
        for (int mi = 0; mi < 4; ++mi) {
            const int row = wr * 64 + mi * 16 + arow_off + l7;
            a_addr[mi] = sa + (uint32_t)(row * PITCHW + akh * 4) * 4u;
        }
        const int bkh     = grp & 1;
        const int bni_off = (grp >> 1) * 8;
        #pragma unroll
        for (int np = 0; np < 4; ++np) {
            const int row = wc * 64 + np * 16 + bni_off + l7;
            b_addr[np] = sb + (uint32_t)(row * PITCHW + bkh * 4) * 4u;
        }
    }

    // ---- main loop: 16 k-atoms, 2-deep register pipeline ----
    float acc[4][8][4];
    #pragma unroll
    for (int mi = 0; mi < 4; ++mi)
        #pragma unroll
        for (int ni = 0; ni < 8; ++ni)
            #pragma unroll
            for (int q = 0; q < 4; ++q)
                acc[mi][ni][q] = 0.0f;

    uint32_t af[2][4][4], bf[2][8][2];

    // prologue: load k-atom 0 into buffer 0
    #pragma unroll
    for (int mi = 0; mi < 4; ++mi)
        ldsm_x4(af[0][mi][0], af[0][mi][1], af[0][mi][2], af[0][mi][3], a_addr[mi]);
    #pragma unroll
    for (int np = 0; np < 4; ++np)
        ldsm_x4(bf[0][2 * np][0], bf[0][2 * np][1],
                bf[0][2 * np + 1][0], bf[0][2 * np + 1][1], b_addr[np]);

    #pragma unroll
    for (int ka = 0; ka < 16; ++ka) {
        const int cur = ka & 1;
        const int nxt = cur ^ 1;
        if (ka < 15) {                       // prefetch k-atom ka+1
            const uint32_t kb = (uint32_t)(ka + 1) * 32u;   // 8 words = 32 bytes
            #pragma unroll
            for (int mi = 0; mi < 4; ++mi)
                ldsm_x4(af[nxt][mi][0], af[nxt][mi][1], af[nxt][mi][2], af[nxt][mi][3],
                        a_addr[mi] + kb);
            #pragma unroll
            for (int np = 0; np < 4; ++np)
                ldsm_x4(bf[nxt][2 * np][0], bf[nxt][2 * np][1],
                        bf[nxt][2 * np + 1][0], bf[nxt][2 * np + 1][1],
                        b_addr[np] + kb);
        }
        #pragma unroll
        for (int mi = 0; mi < 4; ++mi)
            #pragma unroll
            for (int ni = 0; ni < 8; ++ni)
                mma16816(acc[mi][ni][0], acc[mi][ni][1], acc[mi][ni][2], acc[mi][ni][3],
                         af[cur][mi][0], af[cur][mi][1], af[cur][mi][2], af[cur][mi][3],
                         bf[cur][ni][0], bf[cur][ni][1]);
    }
    __syncthreads();   // operand smem free for epilogue buffers

    // ---- epilogue: exp + exact diagonal + row/col sums ----
    // element (mi,ni,q): row = wr*64 + mi*16 + g + (q>>1)*8
    //                    col = wc*64 + ni*8 + t*2 + (q&1)
    float* rbuf = reinterpret_cast<float*>(smem_u);            // [4 wc][128 rows]
    float* cbuf = reinterpret_cast<float*>(smem_u + 4 * 128);  // [2 wr][256 cols]

    const int tile_of_wc = wc >> 1;                 // 0 -> bj0, 1 -> bj1
    const int bj_of_wc   = tile_of_wc ? bj1 : bj0;
    const bool diag      = (bj_of_wc == bi);

    #pragma unroll
    for (int mi = 0; mi < 4; ++mi)
        #pragma unroll
        for (int ni = 0; ni < 8; ++ni)
            #pragma unroll
            for (int q = 0; q < 4; ++q) {
                float e = exp2f((acc[mi][ni][q] - 1.0f) * TEMP_SCALE);
                if (diag) {
                    const int r = wr * 64 + mi * 16 + g + (q >> 1) * 8;
                    const int c = (wc & 1) * 64 + ni * 8 + t * 2 + (q & 1);
                    if (r == c) e = 1.0f;           // s_ii == 1 exactly
                }
                acc[mi][ni][q] = e;
            }

    // row sums: per lane 8 rows (mi x rowhalf), reduce over t-lanes
    #pragma unroll
    for (int mi = 0; mi < 4; ++mi)
        #pragma unroll
        for (int h = 0; h < 2; ++h) {
            float rs = 0.0f;
            #pragma unroll
            for (int ni = 0; ni < 8; ++ni)
                rs += acc[mi][ni][2 * h] + acc[mi][ni][2 * h + 1];
            rs += __shfl_xor_sync(0xffffffffu, rs, 1);
            rs += __shfl_xor_sync(0xffffffffu, rs, 2);
            if (t == 0)
                rbuf[wc * 128 + wr * 64 + mi * 16 + g + h * 8] = rs;
        }

    // col sums: per lane 16 cols (ni x b), reduce over g-lanes
    #pragma unroll
    for (int ni = 0; ni < 8; ++ni)
        #pragma unroll
        for (int b = 0; b < 2; ++b) {
            float cs = 0.0f;
            #pragma unroll
            for (int mi = 0; mi < 4; ++mi)
                cs += acc[mi][ni][b] + acc[mi][ni][2 + b];
            cs += __shfl_xor_sync(0xffffffffu, cs, 4);
            cs += __shfl_xor_sync(0xffffffffu, cs, 8);
            cs += __shfl_xor_sync(0xffffffffu, cs, 16);
            if (g == 0)
                cbuf[wr * 256 + wc * 64 + ni * 8 + t * 2 + b] = cs;
        }
    __syncthreads();

    // final writes: unique writer per g_part cell
    if (tid < 128) {                        // row sums of both tiles
        const int row = tid;
        if (do0)
            g_part[bj0][bi * TM + row] = rbuf[0 * 128 + row] + rbuf[1 * 128 + row];
        g_part[bj1][bi * TM + row] = rbuf[2 * 128 + row] + rbuf[3 * 128 + row];
    }
    {                                       // col sums via symmetry (off-diag only)
        const int col  = tid;               // 0..255
        const int tile = col >> 7;
        const int bj   = tile ? bj1 : bj0;
        if (bj != bi && (tile == 1 || do0))
            g_part[bi][bj * TM + (col & 127)] =
                cbuf[0 * 256 + col] + cbuf[1 * 256 + col];
    }
}

// ---------------------------------------------------------------------------
// Kernel 3: per-row S_i = sum of 128 tile partials (double), log, block-sum.
// ---------------------------------------------------------------------------
__global__ void k_rowreduce() {
    const int r = blockIdx.x * 256 + threadIdx.x;
    double s = 0.0;
    #pragma unroll 8
    for (int j = 0; j < NT; ++j)
        s += (double)g_part[j][r];
    double lr = log(s);

    __shared__ double red[256];
    red[threadIdx.x] = lr;
    __syncthreads();
    #pragma unroll
    for (int off = 128; off; off >>= 1) {
        if (threadIdx.x < off) red[threadIdx.x] += red[threadIdx.x + off];
        __syncthreads();
    }
    if (threadIdx.x == 0) g_bsum[blockIdx.x] = red[0];
}

// ---------------------------------------------------------------------------
// Kernel 4: final mean over 64 block partials.
// ---------------------------------------------------------------------------
__global__ void k_final(float* __restrict__ out) {
    double v = g_bsum[threadIdx.x];
    #pragma unroll
    for (int off = 16; off; off >>= 1)
        v += __shfl_xor_sync(0xffffffffu, v, off);
    __shared__ double w[2];
    if ((threadIdx.x & 31) == 0) w[threadIdx.x >> 5] = v;
    __syncthreads();
    if (threadIdx.x == 0)
        out[0] = (float)((w[0] + w[1]) * (1.0 / (double)N));
}

// ---------------------------------------------------------------------------
#define SMEM_BYTES ((128 + 256) * PITCHW * 4)

extern "C" void kernel_launch(void* const* d_in, const int* in_sizes, int n_in,
                              void* d_out, int out_size) {
    const float* emb = (const float*)d_in[0];
    (void)in_sizes; (void)n_in; (void)out_size;

    cudaFuncSetAttribute(k_tiles, cudaFuncAttributeMaxDynamicSharedMemorySize, SMEM_BYTES);

    k_normalize<<<N / 8, 256>>>(emb);
    dim3 grid(NT / 2, NT);
    k_tiles<<<grid, 256, SMEM_BYTES>>>();
    k_rowreduce<<<N / 256, 256>>>();
    k_final<<<1, 64>>>((float*)d_out);
}